// round 13
// baseline (speedup 1.0000x reference)
#include <cuda_runtime.h>
#include <cuda_fp16.h>
#include <cstdint>

#define Bv 256
#define Tv 150
#define Fv 1024
#define Uv 28
#define G3 84    // 3*U
#define NGRP 10  // ceil(150/16) t-groups per batch

#define LOG2E  1.4426950408889634f

// ---------------- scratch (device globals; no allocation allowed) ----------
// g_C: mma-fragment-ready layout. [b][grp 0..9][k 0..63] chunks of 512B.
// lane*16B in chunk holds {c0,c1,c2,c3} half2s (g=lane>>2, tq=lane&3):
//   c0=C[t0+g][16k+2tq..+1] c1=C[t0+g+8][..] c2=C[t0+g][16k+2tq+8..] c3=[g+8]
// Pad rows (t>=150) stay zero (device globals zero-init, never written).
__device__ uint4  g_C[(size_t)Bv * NGRP * 64 * 32];   // 83.9 MB
__device__ __half g_XG[(size_t)Bv * Tv * G3];         // 6.4 MB (linear)
__device__ __half g_WaS[Bv * Fv];                     // fp16, linear
__device__ __half g_Va16[Fv];                         // Va pre-converted
__device__ float  g_scores[Bv * Tv];
__device__ float  g_h[Bv * Uv];

// ---------------- fast-math helpers ----------------------------------------
__device__ __forceinline__ float ex2f(float x) {
    float y; asm("ex2.approx.ftz.f32 %0, %1;" : "=f"(y) : "f"(x)); return y;
}
__device__ __forceinline__ float rcpf(float x) {
    float y; asm("rcp.approx.ftz.f32 %0, %1;" : "=f"(y) : "f"(x)); return y;
}
__device__ __forceinline__ uint32_t tanh_h2(uint32_t x) {
    uint32_t y;
    asm("tanh.approx.f16x2 %0, %1;" : "=r"(y) : "r"(x));
    return y;
}
__device__ __forceinline__ uint32_t hadd2u(uint32_t a, uint32_t b) {
    __half2 r = __hadd2(*(__half2*)&a, *(__half2*)&b);
    return *(uint32_t*)&r;
}
__device__ __forceinline__ float tanh_acc(float a) {
    float e = ex2f(a * (2.0f * LOG2E));
    return fmaf(-2.0f, rcpf(e + 1.0f), 1.0f);
}
__device__ __forceinline__ float sigmoid_fast(float a) {
    float e = ex2f(-a * LOG2E);
    return rcpf(1.0f + e);
}

// ---------------- init ------------------------------------------------------
__global__ void init_kernel(const float* __restrict__ Va) {
    int i = blockIdx.x * blockDim.x + threadIdx.x;
    if (i < Bv * Fv) g_WaS[i] = __float2half(0.0f);
    if (i < Fv)      g_Va16[i] = __float2half(Va[i]);
    if (i < Bv * Uv) g_h[i] = 0.0f;
}

// ---------------- fragment-layout address (word index into g_C as u32) -----
__device__ __forceinline__ size_t c_word(int row, int col) {
    int b = row / Tv;
    int t = row - b * Tv;
    int grp = t >> 4, gf = t & 15;
    int k = col >> 4, c = col & 15;
    size_t chunk = (size_t)(b * NGRP + grp) * 64 + k;
    int slot = (gf & 7) * 4 + ((c & 7) >> 1);
    return chunk * 128 + slot * 4 + (gf >> 3) + ((c >> 3) << 1);
}

// ---------------- tensor-core GEMM: fp32 in (converted to fp16), fp32 acc --
#define BM 128
#define BN 128
#define BKg 16
#define PITCH 24

__device__ __forceinline__ void mma16816(float* d,
    uint32_t a0, uint32_t a1, uint32_t a2, uint32_t a3,
    uint32_t b0, uint32_t b1)
{
    asm volatile(
        "mma.sync.aligned.m16n8k16.row.col.f32.f16.f16.f32 "
        "{%0,%1,%2,%3}, {%4,%5,%6,%7}, {%8,%9}, {%0,%1,%2,%3};"
        : "+f"(d[0]), "+f"(d[1]), "+f"(d[2]), "+f"(d[3])
        : "r"(a0), "r"(a1), "r"(a2), "r"(a3), "r"(b0), "r"(b1));
}

// scatter=1: write to g_C fragment layout; scatter=0: linear half rows (XG).
__global__ __launch_bounds__(256)
void gemm_mma(const float* __restrict__ A, int lda,
              const float* __restrict__ Bm, int ldb,
              __half* __restrict__ Cm, int ldc, int Ncols,
              const float* __restrict__ bias1,
              const float* __restrict__ bias2,
              int scatter)
{
    __shared__ __align__(16) __half As[BM * PITCH];   // [m][k]
    __shared__ __align__(16) __half Bs[BN * PITCH];   // [n][k]

    int tid = threadIdx.x, lane = tid & 31, wid = tid >> 5;
    int warp_m = wid & 3, warp_n = wid >> 2;
    int bm = blockIdx.y * BM, bn = blockIdx.x * BN;
    int g = lane >> 2, tg = lane & 3;

    int a_row[2], a_kq[2], b_n[2], b_kq[2];
#pragma unroll
    for (int i = 0; i < 2; i++) {
        int fa = tid + 256 * i;
        a_row[i] = fa >> 2; a_kq[i] = fa & 3;
        b_n[i] = fa & 127;  b_kq[i] = fa >> 7;
    }

    float4 pa[2];
    float  pb[2][4];
#pragma unroll
    for (int i = 0; i < 2; i++) {
        pa[i] = *(const float4*)&A[(size_t)(bm + a_row[i]) * lda + a_kq[i] * 4];
        int col = bn + b_n[i];
        bool ok = col < Ncols;
#pragma unroll
        for (int j = 0; j < 4; j++)
            pb[i][j] = ok ? Bm[(size_t)(b_kq[i] * 4 + j) * ldb + col] : 0.0f;
    }

    float acc[2][8][4];
#pragma unroll
    for (int t = 0; t < 2; t++)
#pragma unroll
        for (int j = 0; j < 8; j++)
#pragma unroll
            for (int q = 0; q < 4; q++) acc[t][j][q] = 0.0f;

    const int KT = Fv / BKg;
    for (int kt = 0; kt < KT; kt++) {
        __syncthreads();
#pragma unroll
        for (int i = 0; i < 2; i++) {
            __half2 h0 = __floats2half2_rn(pa[i].x, pa[i].y);
            __half2 h1 = __floats2half2_rn(pa[i].z, pa[i].w);
            *(__half2*)&As[a_row[i] * PITCH + a_kq[i] * 4]     = h0;
            *(__half2*)&As[a_row[i] * PITCH + a_kq[i] * 4 + 2] = h1;
            __half2 g0 = __floats2half2_rn(pb[i][0], pb[i][1]);
            __half2 g1 = __floats2half2_rn(pb[i][2], pb[i][3]);
            *(__half2*)&Bs[b_n[i] * PITCH + b_kq[i] * 4]     = g0;
            *(__half2*)&Bs[b_n[i] * PITCH + b_kq[i] * 4 + 2] = g1;
        }
        if (kt + 1 < KT) {
            int k0 = (kt + 1) * BKg;
#pragma unroll
            for (int i = 0; i < 2; i++) {
                pa[i] = *(const float4*)&A[(size_t)(bm + a_row[i]) * lda + k0 + a_kq[i] * 4];
                int col = bn + b_n[i];
                bool ok = col < Ncols;
#pragma unroll
                for (int j = 0; j < 4; j++)
                    pb[i][j] = ok ? Bm[(size_t)(k0 + b_kq[i] * 4 + j) * ldb + col] : 0.0f;
            }
        }
        __syncthreads();

        uint32_t af[2][4];
#pragma unroll
        for (int t = 0; t < 2; t++) {
            int m = warp_m * 32 + t * 16 + g;
            af[t][0] = *(const uint32_t*)&As[m * PITCH + tg * 2];
            af[t][1] = *(const uint32_t*)&As[(m + 8) * PITCH + tg * 2];
            af[t][2] = *(const uint32_t*)&As[m * PITCH + tg * 2 + 8];
            af[t][3] = *(const uint32_t*)&As[(m + 8) * PITCH + tg * 2 + 8];
        }
#pragma unroll
        for (int j = 0; j < 8; j++) {
            int n = warp_n * 64 + j * 8 + g;
            uint32_t b0 = *(const uint32_t*)&Bs[n * PITCH + tg * 2];
            uint32_t b1 = *(const uint32_t*)&Bs[n * PITCH + tg * 2 + 8];
#pragma unroll
            for (int t = 0; t < 2; t++)
                mma16816(acc[t][j], af[t][0], af[t][1], af[t][2], af[t][3], b0, b1);
        }
    }

#pragma unroll
    for (int t = 0; t < 2; t++) {
        int row = bm + warp_m * 32 + t * 16 + g;
#pragma unroll
        for (int j = 0; j < 8; j++) {
            int col = bn + warp_n * 64 + j * 8 + tg * 2;
            if (col < Ncols) {
                float bb0 = 0.f, bb1 = 0.f;
                if (bias1) {
                    bb0 = bias1[col] + bias2[col];
                    bb1 = bias1[col + 1] + bias2[col + 1];
                }
                __half2 lo = __floats2half2_rn(acc[t][j][0] + bb0, acc[t][j][1] + bb1);
                __half2 hi = __floats2half2_rn(acc[t][j][2] + bb0, acc[t][j][3] + bb1);
                if (scatter) {
                    uint32_t* Cw = (uint32_t*)g_C;
                    Cw[c_word(row, col)]     = *(uint32_t*)&lo;
                    Cw[c_word(row + 8, col)] = *(uint32_t*)&hi;
                } else {
                    *(__half2*)&Cm[(size_t)row * ldc + col]       = lo;
                    *(__half2*)&Cm[(size_t)(row + 8) * ldc + col] = hi;
                }
            }
        }
    }
}

// ---------------- per-step score kernel (tensor-core, single wave) ----------
// Grid (5, 256) = 1280 blocks, each doing TWO t-groups (grp, grp+5) of one b:
// all blocks resident in ONE wave (<=9/SM; R12's 2560-block grid left a
// 192-block second wave = quantization tail). sW/sVa staged once per block.
// Inner loop identical to R12: depth-4 prefetch + dual MMA accumulators.
__global__ __launch_bounds__(128)
void score_kernel()
{
    __shared__ __half sW[Fv];     // 2 KB
    __shared__ __half sVa[Fv];    // 2 KB
    __shared__ float  sD[4][16];

    int gx = blockIdx.x;          // 0..4
    int b = blockIdx.y;
    int tid = threadIdx.x, wid = tid >> 5, lane = tid & 31;
    int g = lane >> 2, tq = lane & 3;

    for (int i = tid; i < Fv / 8; i += 128)
        ((uint4*)sW)[i] = ((const uint4*)(g_WaS + (size_t)b * Fv))[i];
    for (int i = tid; i < Fv / 8; i += 128)
        ((uint4*)sVa)[i] = ((const uint4*)g_Va16)[i];
    __syncthreads();

#pragma unroll
    for (int half = 0; half < 2; half++) {
        int grp = gx + half * 5;  // 0..9
        const uint4* Cp =
            g_C + ((size_t)(b * NGRP + grp) * 64 + wid * 16) * 32 + lane;

        float d0[4] = {0.f, 0.f, 0.f, 0.f};
        float d1[4] = {0.f, 0.f, 0.f, 0.f};

        uint4 buf[4];
#pragma unroll
        for (int i = 0; i < 4; i++) buf[i] = __ldg(Cp + i * 32);

#pragma unroll
        for (int k = 0; k < 16; k++) {
            uint4 cur = buf[k & 3];
            if (k + 4 < 16) buf[k & 3] = __ldg(Cp + (k + 4) * 32);

            int base = (wid * 16 + k) * 16 + tq * 2;
            uint32_t wa = *(const uint32_t*)&sW[base];
            uint32_t wb = *(const uint32_t*)&sW[base + 8];
            uint32_t b0 = *(const uint32_t*)&sVa[base];
            uint32_t b1 = *(const uint32_t*)&sVa[base + 8];

            uint32_t a0 = tanh_h2(hadd2u(cur.x, wa));
            uint32_t a1 = tanh_h2(hadd2u(cur.y, wa));
            uint32_t a2 = tanh_h2(hadd2u(cur.z, wb));
            uint32_t a3 = tanh_h2(hadd2u(cur.w, wb));

            mma16816((k & 1) ? d1 : d0, a0, a1, a2, a3, b0, b1);
        }

        if (tq == 0) {                  // [0]=D[g][0], [2]=D[g+8][0]
            sD[wid][g]     = d0[0] + d1[0];
            sD[wid][g + 8] = d0[2] + d1[2];
        }
        __syncthreads();
        if (tid < 16) {
            int t = grp * 16 + tid;
            if (t < Tv)
                g_scores[b * Tv + t] =
                    (sD[0][tid] + sD[1][tid]) + (sD[2][tid] + sD[3][tid]);
        }
        __syncthreads();
    }
}

// ---------------- per-step softmax + GRU + next WaS (1 block per batch b) --
__global__ __launch_bounds__(256)
void att_gru_kernel(const float* __restrict__ Wa,
                    const float* __restrict__ grk,
                    const float* __restrict__ gb,
                    float* __restrict__ out, int tstep)
{
    int b = blockIdx.x, tid = threadIdx.x;

    __shared__ float sa[Tv];
    __shared__ float red[256];
    __shared__ float spart[3 * G3];
    __shared__ float sxz[G3], shz[G3];
    __shared__ float sh[Uv], shnew[Uv];

    if (tid < Uv) sh[tid] = g_h[b * Uv + tid];

    float v = (tid < Tv) ? g_scores[b * Tv + tid] : -1e30f;
    red[tid] = v;
    __syncthreads();
#pragma unroll
    for (int s = 128; s > 0; s >>= 1) {
        if (tid < s) red[tid] = fmaxf(red[tid], red[tid + s]);
        __syncthreads();
    }
    float mx = red[0];
    __syncthreads();
    float e = 0.0f;
    if (tid < Tv) e = ex2f((v - mx) * LOG2E);
    red[tid] = e;
    __syncthreads();
#pragma unroll
    for (int s = 128; s > 0; s >>= 1) {
        if (tid < s) red[tid] += red[tid + s];
        __syncthreads();
    }
    float inv = rcpf(red[0]);
    if (tid < Tv) sa[tid] = e * inv;
    __syncthreads();

    int part = tid / G3;        // 0..2 used; tid>=252 idle
    int j = tid - part * G3;
    if (part < 3) {
        float acc = 0.0f;
        const __half* XGb = g_XG + (size_t)b * Tv * G3 + j;
        for (int t = part; t < Tv; t += 3)
            acc = fmaf(sa[t], __half2float(XGb[t * G3]), acc);
        spart[part * G3 + j] = acc;
    }
    __syncthreads();

    if (tid < G3) {
        float xz = gb[tid] + spart[tid] + spart[G3 + tid] + spart[2 * G3 + tid];
        float hzv = gb[G3 + tid];
#pragma unroll
        for (int u = 0; u < Uv; u++)
            hzv = fmaf(sh[u], grk[u * G3 + tid], hzv);
        sxz[tid] = xz;
        shz[tid] = hzv;
    }
    __syncthreads();

    if (tid < Uv) {
        float z  = sigmoid_fast(sxz[tid]          + shz[tid]);
        float r  = sigmoid_fast(sxz[Uv + tid]     + shz[Uv + tid]);
        float hh = tanh_acc    (sxz[2 * Uv + tid] + r * shz[2 * Uv + tid]);
        float hn = hh + z * (sh[tid] - hh);
        g_h[b * Uv + tid] = hn;
        out[((size_t)b * Tv + tstep) * Uv + tid] = hn;
        shnew[tid] = hn;
    }
    __syncthreads();

    float4 w = make_float4(0.f, 0.f, 0.f, 0.f);
    const float4* Wa4 = (const float4*)Wa;
#pragma unroll
    for (int u = 0; u < Uv; u++) {
        float hv = shnew[u];
        float4 wv = Wa4[u * (Fv / 4) + tid];
        w.x = fmaf(hv, wv.x, w.x);
        w.y = fmaf(hv, wv.y, w.y);
        w.z = fmaf(hv, wv.z, w.z);
        w.w = fmaf(hv, wv.w, w.w);
    }
    __half2 p0 = __floats2half2_rn(w.x, w.y);
    __half2 p1 = __floats2half2_rn(w.z, w.w);
    uint2 pk;
    pk.x = *(uint32_t*)&p0;
    pk.y = *(uint32_t*)&p1;
    ((uint2*)g_WaS)[b * (Fv / 4) + tid] = pk;
}

// ---------------- launch -----------------------------------------------------
extern "C" void kernel_launch(void* const* d_in, const int* in_sizes, int n_in,
                              void* d_out, int out_size)
{
    const float* x   = (const float*)d_in[0];  // (B,T,F)
    const float* Wa  = (const float*)d_in[1];  // (U,F)
    const float* Ua  = (const float*)d_in[2];  // (F,F)
    const float* Va  = (const float*)d_in[3];  // (F,1)
    const float* Ba1 = (const float*)d_in[4];  // (1,F)
    const float* Ba2 = (const float*)d_in[5];  // (1,F)
    // d_in[6] = Ba3 : softmax-invariant, unused
    const float* gk  = (const float*)d_in[7];  // (F,3U)
    const float* grk = (const float*)d_in[8];  // (U,3U)
    const float* gb  = (const float*)d_in[9];  // (2,3U)
    float* out = (float*)d_out;                // (B,T,U)

    init_kernel<<<(Bv * Fv + 255) / 256, 256>>>(Va);

    __half* XGm; cudaGetSymbolAddress((void**)&XGm, g_XG);

    // C = x @ Ua + Ba1 + Ba2  -> g_C fragment layout (scatter=1)
    gemm_mma<<<dim3(Fv / BN, (Bv * Tv) / BM), 256>>>(
        x, Fv, Ua, Fv, nullptr, 0, Fv, Ba1, Ba2, 1);
    // XG = x @ gru_kernel     -> linear fp16 (scatter=0)
    gemm_mma<<<dim3(1, (Bv * Tv) / BM), 256>>>(
        x, Fv, gk, G3, XGm, G3, G3, nullptr, nullptr, 0);

    dim3 sgrid(NGRP / 2, Bv);   // (5, 256) = 1280 blocks: ONE wave
    for (int t = 0; t < Tv; t++) {
        score_kernel<<<sgrid, 128>>>();
        att_gru_kernel<<<Bv, 256>>>(Wa, grk, gb, out, t);
    }
}

// round 14
// speedup vs baseline: 1.0964x; 1.0964x over previous
#include <cuda_runtime.h>
#include <cuda_fp16.h>
#include <cstdint>

#define Bv 256
#define Tv 150
#define Fv 1024
#define Uv 28
#define G3 84    // 3*U
#define NGRP 10  // ceil(150/16) t-groups per batch

#define LOG2E  1.4426950408889634f

// ---------------- scratch (device globals; no allocation allowed) ----------
// g_C: mma-fragment-ready layout. [b][grp 0..9][k 0..63] chunks of 512B.
// lane*16B in chunk holds {c0,c1,c2,c3} half2s (g=lane>>2, tq=lane&3):
//   c0=C[t0+g][16k+2tq..+1] c1=C[t0+g+8][..] c2=C[t0+g][16k+2tq+8..] c3=[g+8]
// Pad rows (t>=150) stay zero (device globals zero-init, never written).
__device__ uint4  g_C[(size_t)Bv * NGRP * 64 * 32];   // 83.9 MB
__device__ __half g_XG[(size_t)Bv * Tv * G3];         // 6.4 MB (linear)
__device__ __half g_WaS[Bv * Fv];                     // fp16, linear
__device__ __half g_Va16[Fv];                         // Va pre-converted
__device__ float  g_scores[Bv * Tv];
__device__ float  g_h[Bv * Uv];

// ---------------- fast-math helpers ----------------------------------------
__device__ __forceinline__ float ex2f(float x) {
    float y; asm("ex2.approx.ftz.f32 %0, %1;" : "=f"(y) : "f"(x)); return y;
}
__device__ __forceinline__ float rcpf(float x) {
    float y; asm("rcp.approx.ftz.f32 %0, %1;" : "=f"(y) : "f"(x)); return y;
}
__device__ __forceinline__ uint32_t tanh_h2(uint32_t x) {
    uint32_t y;
    asm("tanh.approx.f16x2 %0, %1;" : "=r"(y) : "r"(x));
    return y;
}
__device__ __forceinline__ uint32_t hadd2u(uint32_t a, uint32_t b) {
    __half2 r = __hadd2(*(__half2*)&a, *(__half2*)&b);
    return *(uint32_t*)&r;
}
__device__ __forceinline__ float tanh_acc(float a) {
    float e = ex2f(a * (2.0f * LOG2E));
    return fmaf(-2.0f, rcpf(e + 1.0f), 1.0f);
}
__device__ __forceinline__ float sigmoid_fast(float a) {
    float e = ex2f(-a * LOG2E);
    return rcpf(1.0f + e);
}

// ---------------- init ------------------------------------------------------
__global__ void init_kernel(const float* __restrict__ Va) {
    int i = blockIdx.x * blockDim.x + threadIdx.x;
    if (i < Bv * Fv) g_WaS[i] = __float2half(0.0f);
    if (i < Fv)      g_Va16[i] = __float2half(Va[i]);
    if (i < Bv * Uv) g_h[i] = 0.0f;
}

// ---------------- fragment-layout address (word index into g_C as u32) -----
__device__ __forceinline__ size_t c_word(int row, int col) {
    int b = row / Tv;
    int t = row - b * Tv;
    int grp = t >> 4, gf = t & 15;
    int k = col >> 4, c = col & 15;
    size_t chunk = (size_t)(b * NGRP + grp) * 64 + k;
    int slot = (gf & 7) * 4 + ((c & 7) >> 1);
    return chunk * 128 + slot * 4 + (gf >> 3) + ((c >> 3) << 1);
}

// ---------------- tensor-core GEMM: fp32 in (converted to fp16), fp32 acc --
#define BM 128
#define BN 128
#define BKg 16
#define PITCH 24

__device__ __forceinline__ void mma16816(float* d,
    uint32_t a0, uint32_t a1, uint32_t a2, uint32_t a3,
    uint32_t b0, uint32_t b1)
{
    asm volatile(
        "mma.sync.aligned.m16n8k16.row.col.f32.f16.f16.f32 "
        "{%0,%1,%2,%3}, {%4,%5,%6,%7}, {%8,%9}, {%0,%1,%2,%3};"
        : "+f"(d[0]), "+f"(d[1]), "+f"(d[2]), "+f"(d[3])
        : "r"(a0), "r"(a1), "r"(a2), "r"(a3), "r"(b0), "r"(b1));
}

// scatter=1: write to g_C fragment layout; scatter=0: linear half rows (XG).
__global__ __launch_bounds__(256)
void gemm_mma(const float* __restrict__ A, int lda,
              const float* __restrict__ Bm, int ldb,
              __half* __restrict__ Cm, int ldc, int Ncols,
              const float* __restrict__ bias1,
              const float* __restrict__ bias2,
              int scatter)
{
    __shared__ __align__(16) __half As[BM * PITCH];   // [m][k]
    __shared__ __align__(16) __half Bs[BN * PITCH];   // [n][k]

    int tid = threadIdx.x, lane = tid & 31, wid = tid >> 5;
    int warp_m = wid & 3, warp_n = wid >> 2;
    int bm = blockIdx.y * BM, bn = blockIdx.x * BN;
    int g = lane >> 2, tg = lane & 3;

    int a_row[2], a_kq[2], b_n[2], b_kq[2];
#pragma unroll
    for (int i = 0; i < 2; i++) {
        int fa = tid + 256 * i;
        a_row[i] = fa >> 2; a_kq[i] = fa & 3;
        b_n[i] = fa & 127;  b_kq[i] = fa >> 7;
    }

    float4 pa[2];
    float  pb[2][4];
#pragma unroll
    for (int i = 0; i < 2; i++) {
        pa[i] = *(const float4*)&A[(size_t)(bm + a_row[i]) * lda + a_kq[i] * 4];
        int col = bn + b_n[i];
        bool ok = col < Ncols;
#pragma unroll
        for (int j = 0; j < 4; j++)
            pb[i][j] = ok ? Bm[(size_t)(b_kq[i] * 4 + j) * ldb + col] : 0.0f;
    }

    float acc[2][8][4];
#pragma unroll
    for (int t = 0; t < 2; t++)
#pragma unroll
        for (int j = 0; j < 8; j++)
#pragma unroll
            for (int q = 0; q < 4; q++) acc[t][j][q] = 0.0f;

    const int KT = Fv / BKg;
    for (int kt = 0; kt < KT; kt++) {
        __syncthreads();
#pragma unroll
        for (int i = 0; i < 2; i++) {
            __half2 h0 = __floats2half2_rn(pa[i].x, pa[i].y);
            __half2 h1 = __floats2half2_rn(pa[i].z, pa[i].w);
            *(__half2*)&As[a_row[i] * PITCH + a_kq[i] * 4]     = h0;
            *(__half2*)&As[a_row[i] * PITCH + a_kq[i] * 4 + 2] = h1;
            __half2 g0 = __floats2half2_rn(pb[i][0], pb[i][1]);
            __half2 g1 = __floats2half2_rn(pb[i][2], pb[i][3]);
            *(__half2*)&Bs[b_n[i] * PITCH + b_kq[i] * 4]     = g0;
            *(__half2*)&Bs[b_n[i] * PITCH + b_kq[i] * 4 + 2] = g1;
        }
        if (kt + 1 < KT) {
            int k0 = (kt + 1) * BKg;
#pragma unroll
            for (int i = 0; i < 2; i++) {
                pa[i] = *(const float4*)&A[(size_t)(bm + a_row[i]) * lda + k0 + a_kq[i] * 4];
                int col = bn + b_n[i];
                bool ok = col < Ncols;
#pragma unroll
                for (int j = 0; j < 4; j++)
                    pb[i][j] = ok ? Bm[(size_t)(k0 + b_kq[i] * 4 + j) * ldb + col] : 0.0f;
            }
        }
        __syncthreads();

        uint32_t af[2][4];
#pragma unroll
        for (int t = 0; t < 2; t++) {
            int m = warp_m * 32 + t * 16 + g;
            af[t][0] = *(const uint32_t*)&As[m * PITCH + tg * 2];
            af[t][1] = *(const uint32_t*)&As[(m + 8) * PITCH + tg * 2];
            af[t][2] = *(const uint32_t*)&As[m * PITCH + tg * 2 + 8];
            af[t][3] = *(const uint32_t*)&As[(m + 8) * PITCH + tg * 2 + 8];
        }
#pragma unroll
        for (int j = 0; j < 8; j++) {
            int n = warp_n * 64 + j * 8 + g;
            uint32_t b0 = *(const uint32_t*)&Bs[n * PITCH + tg * 2];
            uint32_t b1 = *(const uint32_t*)&Bs[n * PITCH + tg * 2 + 8];
#pragma unroll
            for (int t = 0; t < 2; t++)
                mma16816(acc[t][j], af[t][0], af[t][1], af[t][2], af[t][3], b0, b1);
        }
    }

#pragma unroll
    for (int t = 0; t < 2; t++) {
        int row = bm + warp_m * 32 + t * 16 + g;
#pragma unroll
        for (int j = 0; j < 8; j++) {
            int col = bn + warp_n * 64 + j * 8 + tg * 2;
            if (col < Ncols) {
                float bb0 = 0.f, bb1 = 0.f;
                if (bias1) {
                    bb0 = bias1[col] + bias2[col];
                    bb1 = bias1[col + 1] + bias2[col + 1];
                }
                __half2 lo = __floats2half2_rn(acc[t][j][0] + bb0, acc[t][j][1] + bb1);
                __half2 hi = __floats2half2_rn(acc[t][j][2] + bb0, acc[t][j][3] + bb1);
                if (scatter) {
                    uint32_t* Cw = (uint32_t*)g_C;
                    Cw[c_word(row, col)]     = *(uint32_t*)&lo;
                    Cw[c_word(row + 8, col)] = *(uint32_t*)&hi;
                } else {
                    *(__half2*)&Cm[(size_t)row * ldc + col]       = lo;
                    *(__half2*)&Cm[(size_t)(row + 8) * ldc + col] = hi;
                }
            }
        }
    }
}

// ---------------- per-step score kernel (tensor-core, K-split 4 warps) ------
// R12 structure (grid 2560, the measured best: occ 87%) + packed-operand
// diet: {wa,wb,b0,b1} for each (k,tq) pre-packed into ONE smem uint4 ->
// 1 LDS.128 per k replaces 4 LDS.32 (issue/LSU slots -20%).
__global__ __launch_bounds__(128)
void score_kernel()
{
    __shared__ uint4 sWV[256];    // 4 KB: [k 0..63][tq 0..3] = {wa,wb,b0,b1}
    __shared__ float sD[4][16];

    int grp = blockIdx.x;         // 0..9
    int b = blockIdx.y;
    int tid = threadIdx.x, wid = tid >> 5, lane = tid & 31;
    int g = lane >> 2, tq = lane & 3;

    {
        const uint32_t* Wp = (const uint32_t*)(g_WaS + (size_t)b * Fv);
        const uint32_t* Vp = (const uint32_t*)g_Va16;
#pragma unroll
        for (int e = tid; e < 256; e += 128) {
            int w32 = (e >> 2) * 8 + (e & 3);   // uint32 index of half-pair base
            uint4 wv;
            wv.x = Wp[w32];
            wv.y = Wp[w32 + 4];
            wv.z = Vp[w32];
            wv.w = Vp[w32 + 4];
            sWV[e] = wv;
        }
    }
    __syncthreads();

    const uint4* Cp = g_C + ((size_t)(b * NGRP + grp) * 64 + wid * 16) * 32 + lane;

    float d0[4] = {0.f, 0.f, 0.f, 0.f};
    float d1[4] = {0.f, 0.f, 0.f, 0.f};

    uint4 buf[4];
#pragma unroll
    for (int i = 0; i < 4; i++) buf[i] = __ldg(Cp + i * 32);

#pragma unroll
    for (int k = 0; k < 16; k++) {
        uint4 cur = buf[k & 3];
        if (k + 4 < 16) buf[k & 3] = __ldg(Cp + (k + 4) * 32);

        uint4 wv = sWV[(wid * 16 + k) * 4 + tq];

        uint32_t a0 = tanh_h2(hadd2u(cur.x, wv.x));
        uint32_t a1 = tanh_h2(hadd2u(cur.y, wv.x));
        uint32_t a2 = tanh_h2(hadd2u(cur.z, wv.y));
        uint32_t a3 = tanh_h2(hadd2u(cur.w, wv.y));

        mma16816((k & 1) ? d1 : d0, a0, a1, a2, a3, wv.z, wv.w);
    }

    if (tq == 0) {                      // [0]=D[g][0], [2]=D[g+8][0]
        sD[wid][g]     = d0[0] + d1[0];
        sD[wid][g + 8] = d0[2] + d1[2];
    }
    __syncthreads();
    if (tid < 16) {
        int t = grp * 16 + tid;
        if (t < Tv)
            g_scores[b * Tv + t] =
                (sD[0][tid] + sD[1][tid]) + (sD[2][tid] + sD[3][tid]);
    }
}

// ---------------- per-step softmax + GRU + next WaS (1 block per batch b) --
__global__ __launch_bounds__(256)
void att_gru_kernel(const float* __restrict__ Wa,
                    const float* __restrict__ grk,
                    const float* __restrict__ gb,
                    float* __restrict__ out, int tstep)
{
    int b = blockIdx.x, tid = threadIdx.x;

    __shared__ float sa[Tv];
    __shared__ float red[256];
    __shared__ float spart[3 * G3];
    __shared__ float sxz[G3], shz[G3];
    __shared__ float sh[Uv], shnew[Uv];

    if (tid < Uv) sh[tid] = g_h[b * Uv + tid];

    float v = (tid < Tv) ? g_scores[b * Tv + tid] : -1e30f;
    red[tid] = v;
    __syncthreads();
#pragma unroll
    for (int s = 128; s > 0; s >>= 1) {
        if (tid < s) red[tid] = fmaxf(red[tid], red[tid + s]);
        __syncthreads();
    }
    float mx = red[0];
    __syncthreads();
    float e = 0.0f;
    if (tid < Tv) e = ex2f((v - mx) * LOG2E);
    red[tid] = e;
    __syncthreads();
#pragma unroll
    for (int s = 128; s > 0; s >>= 1) {
        if (tid < s) red[tid] += red[tid + s];
        __syncthreads();
    }
    float inv = rcpf(red[0]);
    if (tid < Tv) sa[tid] = e * inv;
    __syncthreads();

    int part = tid / G3;        // 0..2 used; tid>=252 idle
    int j = tid - part * G3;
    if (part < 3) {
        float acc = 0.0f;
        const __half* XGb = g_XG + (size_t)b * Tv * G3 + j;
        for (int t = part; t < Tv; t += 3)
            acc = fmaf(sa[t], __half2float(XGb[t * G3]), acc);
        spart[part * G3 + j] = acc;
    }
    __syncthreads();

    if (tid < G3) {
        float xz = gb[tid] + spart[tid] + spart[G3 + tid] + spart[2 * G3 + tid];
        float hzv = gb[G3 + tid];
#pragma unroll
        for (int u = 0; u < Uv; u++)
            hzv = fmaf(sh[u], grk[u * G3 + tid], hzv);
        sxz[tid] = xz;
        shz[tid] = hzv;
    }
    __syncthreads();

    if (tid < Uv) {
        float z  = sigmoid_fast(sxz[tid]          + shz[tid]);
        float r  = sigmoid_fast(sxz[Uv + tid]     + shz[Uv + tid]);
        float hh = tanh_acc    (sxz[2 * Uv + tid] + r * shz[2 * Uv + tid]);
        float hn = hh + z * (sh[tid] - hh);
        g_h[b * Uv + tid] = hn;
        out[((size_t)b * Tv + tstep) * Uv + tid] = hn;
        shnew[tid] = hn;
    }
    __syncthreads();

    float4 w = make_float4(0.f, 0.f, 0.f, 0.f);
    const float4* Wa4 = (const float4*)Wa;
#pragma unroll
    for (int u = 0; u < Uv; u++) {
        float hv = shnew[u];
        float4 wv = Wa4[u * (Fv / 4) + tid];
        w.x = fmaf(hv, wv.x, w.x);
        w.y = fmaf(hv, wv.y, w.y);
        w.z = fmaf(hv, wv.z, w.z);
        w.w = fmaf(hv, wv.w, w.w);
    }
    __half2 p0 = __floats2half2_rn(w.x, w.y);
    __half2 p1 = __floats2half2_rn(w.z, w.w);
    uint2 pk;
    pk.x = *(uint32_t*)&p0;
    pk.y = *(uint32_t*)&p1;
    ((uint2*)g_WaS)[b * (Fv / 4) + tid] = pk;
}

// ---------------- launch -----------------------------------------------------
extern "C" void kernel_launch(void* const* d_in, const int* in_sizes, int n_in,
                              void* d_out, int out_size)
{
    const float* x   = (const float*)d_in[0];  // (B,T,F)
    const float* Wa  = (const float*)d_in[1];  // (U,F)
    const float* Ua  = (const float*)d_in[2];  // (F,F)
    const float* Va  = (const float*)d_in[3];  // (F,1)
    const float* Ba1 = (const float*)d_in[4];  // (1,F)
    const float* Ba2 = (const float*)d_in[5];  // (1,F)
    // d_in[6] = Ba3 : softmax-invariant, unused
    const float* gk  = (const float*)d_in[7];  // (F,3U)
    const float* grk = (const float*)d_in[8];  // (U,3U)
    const float* gb  = (const float*)d_in[9];  // (2,3U)
    float* out = (float*)d_out;                // (B,T,U)

    init_kernel<<<(Bv * Fv + 255) / 256, 256>>>(Va);

    __half* XGm; cudaGetSymbolAddress((void**)&XGm, g_XG);

    // C = x @ Ua + Ba1 + Ba2  -> g_C fragment layout (scatter=1)
    gemm_mma<<<dim3(Fv / BN, (Bv * Tv) / BM), 256>>>(
        x, Fv, Ua, Fv, nullptr, 0, Fv, Ba1, Ba2, 1);
    // XG = x @ gru_kernel     -> linear fp16 (scatter=0)
    gemm_mma<<<dim3(1, (Bv * Tv) / BM), 256>>>(
        x, Fv, gk, G3, XGm, G3, G3, nullptr, nullptr, 0);

    dim3 sgrid(NGRP, Bv);   // (10, 256) = 2560 blocks: R12's measured-best shape
    for (int t = 0; t < Tv; t++) {
        score_kernel<<<sgrid, 128>>>();
        att_gru_kernel<<<Bv, 256>>>(Wa, grk, gb, out, t);
    }
}